// round 2
// baseline (speedup 1.0000x reference)
#include <cuda_runtime.h>

#define NB   1024
#define NP   9
#define ND   2700
#define NDFF 512
#define NM   (NB * NP)            /* 9216 rows */
#define TEPS 1e-5f
#define MDSZ ((size_t)NM * (size_t)ND)   /* 24,883,200 elems per matrix */

/* Scratch: mod{q,k,v} and {q,k,v}. ~597 MB of __device__ statics (allowed). */
__device__ float g_mod[3ULL * NM * ND];
__device__ float g_qkv[3ULL * NM * ND];

struct AuxP {
    const float* WC1[3];
    const float* WC2[3];
    const float* bC1[3];
    const float* bC2[3];
};
struct MainP {
    const float* W[3];
    const float* bias[3];
};

/* ------------------------------------------------------------------ */
/* Kernel 1: mod = H1@WC1 + H2@WC2 + bC1 + bC2   (M=9216, N=2700, K=512+512)
 * 128x128 tile, 256 threads, 8x8 micro-tile, KT=8.                    */
/* ------------------------------------------------------------------ */
__global__ __launch_bounds__(256, 2)
void aux_gemm(const float* __restrict__ H1, const float* __restrict__ H2, AuxP p)
{
    __shared__ float As[8][128];
    __shared__ float Bs[8][128];

    const int zi = blockIdx.z;
    const int m0 = blockIdx.y * 128;
    const int n0 = blockIdx.x * 128;
    const int tid = threadIdx.x;

    float acc[8][8];
#pragma unroll
    for (int i = 0; i < 8; i++)
#pragma unroll
        for (int j = 0; j < 8; j++) acc[i][j] = 0.f;

    const int ar  = tid >> 1;          /* A row within tile (0..127)  */
    const int akq = (tid & 1) * 4;     /* A k-quad (0 or 4)           */
    const int br  = tid >> 5;          /* B k-row (0..7)              */
    const int bc  = (tid & 31) * 4;    /* B col quad                  */
    const int tx  = tid & 15;
    const int ty  = tid >> 4;

    for (int src = 0; src < 2; ++src) {
        const float* Ap = src ? H2 : H1;
        const float* Wp = src ? p.WC2[zi] : p.WC1[zi];
        for (int k0 = 0; k0 < NDFF; k0 += 8) {
            /* global loads */
            float4 av = *(const float4*)(Ap + (size_t)(m0 + ar) * NDFF + k0 + akq);
            float4 bv = make_float4(0.f, 0.f, 0.f, 0.f);
            {
                const int n = n0 + bc;
                const float* wr = Wp + (size_t)(k0 + br) * ND;
                if (n + 3 < ND) {
                    bv = *(const float4*)(wr + n);
                } else {
                    float t[4] = {0.f, 0.f, 0.f, 0.f};
                    for (int q = 0; q < 4; q++)
                        if (n + q < ND) t[q] = wr[n + q];
                    bv = make_float4(t[0], t[1], t[2], t[3]);
                }
            }
            As[akq + 0][ar] = av.x;
            As[akq + 1][ar] = av.y;
            As[akq + 2][ar] = av.z;
            As[akq + 3][ar] = av.w;
            *(float4*)&Bs[br][bc] = bv;
            __syncthreads();

#pragma unroll
            for (int kk = 0; kk < 8; kk++) {
                float a[8], b[8];
#pragma unroll
                for (int i = 0; i < 8; i++) a[i] = As[kk][ty * 8 + i];
#pragma unroll
                for (int j = 0; j < 8; j++) b[j] = Bs[kk][tx * 8 + j];
#pragma unroll
                for (int i = 0; i < 8; i++)
#pragma unroll
                    for (int j = 0; j < 8; j++)
                        acc[i][j] = fmaf(a[i], b[j], acc[i][j]);
            }
            __syncthreads();
        }
    }

    const float* b1 = p.bC1[zi];
    const float* b2 = p.bC2[zi];
#pragma unroll
    for (int i = 0; i < 8; i++) {
        const int m = m0 + ty * 8 + i;
        float* dst = g_mod + (size_t)zi * MDSZ + (size_t)m * ND;
#pragma unroll
        for (int j = 0; j < 8; j++) {
            const int n = n0 + tx * 8 + j;
            if (n < ND) dst[n] = acc[i][j] + b1[n] + b2[n];
        }
    }
}

/* ------------------------------------------------------------------ */
/* Kernel 2: qkv = (x @ W + b) * mod   (M=9216, N=2700, K=2700)        */
/* ------------------------------------------------------------------ */
__global__ __launch_bounds__(256, 2)
void main_gemm(const float* __restrict__ X, MainP p)
{
    __shared__ float As[8][128];
    __shared__ float Bs[8][128];

    const int zi = blockIdx.z;
    const int m0 = blockIdx.y * 128;
    const int n0 = blockIdx.x * 128;
    const int tid = threadIdx.x;

    float acc[8][8];
#pragma unroll
    for (int i = 0; i < 8; i++)
#pragma unroll
        for (int j = 0; j < 8; j++) acc[i][j] = 0.f;

    const int ar  = tid >> 1;
    const int akq = (tid & 1) * 4;
    const int br  = tid >> 5;
    const int bc  = (tid & 31) * 4;
    const int tx  = tid & 15;
    const int ty  = tid >> 4;

    const float* Wp = p.W[zi];

    for (int k0 = 0; k0 < ND; k0 += 8) {      /* 338 tiles; last is partial */
        float4 av = make_float4(0.f, 0.f, 0.f, 0.f);
        {
            const int k = k0 + akq;
            const float* xr = X + (size_t)(m0 + ar) * ND;
            if (k + 3 < ND) {
                av = *(const float4*)(xr + k);
            } else {
                float t[4] = {0.f, 0.f, 0.f, 0.f};
                for (int q = 0; q < 4; q++)
                    if (k + q < ND) t[q] = xr[k + q];
                av = make_float4(t[0], t[1], t[2], t[3]);
            }
        }
        float4 bv = make_float4(0.f, 0.f, 0.f, 0.f);
        if (k0 + br < ND) {
            const int n = n0 + bc;
            const float* wr = Wp + (size_t)(k0 + br) * ND;
            if (n + 3 < ND) {
                bv = *(const float4*)(wr + n);
            } else {
                float t[4] = {0.f, 0.f, 0.f, 0.f};
                for (int q = 0; q < 4; q++)
                    if (n + q < ND) t[q] = wr[n + q];
                bv = make_float4(t[0], t[1], t[2], t[3]);
            }
        }
        As[akq + 0][ar] = av.x;
        As[akq + 1][ar] = av.y;
        As[akq + 2][ar] = av.z;
        As[akq + 3][ar] = av.w;
        *(float4*)&Bs[br][bc] = bv;
        __syncthreads();

#pragma unroll
        for (int kk = 0; kk < 8; kk++) {
            float a[8], b[8];
#pragma unroll
            for (int i = 0; i < 8; i++) a[i] = As[kk][ty * 8 + i];
#pragma unroll
            for (int j = 0; j < 8; j++) b[j] = Bs[kk][tx * 8 + j];
#pragma unroll
            for (int i = 0; i < 8; i++)
#pragma unroll
                for (int j = 0; j < 8; j++)
                    acc[i][j] = fmaf(a[i], b[j], acc[i][j]);
        }
        __syncthreads();
    }

    const float* bias = p.bias[zi];
#pragma unroll
    for (int i = 0; i < 8; i++) {
        const int m = m0 + ty * 8 + i;
        const float* mp = g_mod + (size_t)zi * MDSZ + (size_t)m * ND;
        float* dst = g_qkv + (size_t)zi * MDSZ + (size_t)m * ND;
#pragma unroll
        for (int j = 0; j < 8; j++) {
            const int n = n0 + tx * 8 + j;
            if (n < ND) dst[n] = (acc[i][j] + bias[n]) * mp[n];
        }
    }
}

/* ------------------------------------------------------------------ */
/* Kernel 3: per-batch attention (9x9), residual, LayerNorm.           */
/* One block per batch, 256 threads, z staged in 97 KB dyn smem.       */
/* ------------------------------------------------------------------ */
__global__ __launch_bounds__(256)
void attn_ln(const float* __restrict__ X, const float* __restrict__ gamma,
             const float* __restrict__ beta, float* __restrict__ out)
{
    extern __shared__ float zsh[];     /* NP * ND floats */
    __shared__ float sc[96];           /* scores -> softmax weights */
    __shared__ float red[256];

    const int b   = blockIdx.x;
    const int tid = threadIdx.x;
    const int lane = tid & 31;
    const int w    = tid >> 5;

    const float* q  = g_qkv +               (size_t)b * NP * ND;
    const float* kx = g_qkv + MDSZ +        (size_t)b * NP * ND;
    const float* v  = g_qkv + 2 * MDSZ +    (size_t)b * NP * ND;
    const float* xb = X +                   (size_t)b * NP * ND;

    /* scores: warp per (i,j) pair */
    const float scale = rsqrtf((float)ND);
    for (int pr = w; pr < 81; pr += 8) {
        const int i = pr / 9, j = pr % 9;
        const float* qi = q + i * ND;
        const float* kj = kx + j * ND;
        float s = 0.f;
        for (int d = lane; d < ND; d += 32) s = fmaf(qi[d], kj[d], s);
#pragma unroll
        for (int o = 16; o; o >>= 1) s += __shfl_xor_sync(0xffffffffu, s, o);
        if (lane == 0) sc[pr] = s * scale;
    }
    __syncthreads();

    /* softmax: one thread per query row */
    if (tid < 9) {
        float mx = -1e30f;
#pragma unroll
        for (int j = 0; j < 9; j++) mx = fmaxf(mx, sc[tid * 9 + j]);
        float e[9], sum = 0.f;
#pragma unroll
        for (int j = 0; j < 9; j++) { e[j] = expf(sc[tid * 9 + j] - mx); sum += e[j]; }
        const float inv = 1.f / sum;
#pragma unroll
        for (int j = 0; j < 9; j++) sc[tid * 9 + j] = e[j] * inv;
    }
    __syncthreads();

    /* attn + residual into smem */
    for (int d = tid; d < ND; d += 256) {
        float vj[9];
#pragma unroll
        for (int j = 0; j < 9; j++) vj[j] = v[j * ND + d];
#pragma unroll
        for (int i = 0; i < 9; i++) {
            float a = xb[i * ND + d];
#pragma unroll
            for (int j = 0; j < 9; j++) a = fmaf(sc[i * 9 + j], vj[j], a);
            zsh[i * ND + d] = a;
        }
    }
    __syncthreads();

    /* per-row two-pass LayerNorm */
    for (int i = 0; i < 9; i++) {
        float s = 0.f;
        for (int d = tid; d < ND; d += 256) s += zsh[i * ND + d];
        red[tid] = s; __syncthreads();
        for (int o = 128; o > 0; o >>= 1) {
            if (tid < o) red[tid] += red[tid + o];
            __syncthreads();
        }
        const float mu = red[0] * (1.f / ND);
        __syncthreads();

        float s2 = 0.f;
        for (int d = tid; d < ND; d += 256) {
            const float t = zsh[i * ND + d] - mu;
            s2 = fmaf(t, t, s2);
        }
        red[tid] = s2; __syncthreads();
        for (int o = 128; o > 0; o >>= 1) {
            if (tid < o) red[tid] += red[tid + o];
            __syncthreads();
        }
        const float rstd = rsqrtf(red[0] * (1.f / ND) + TEPS);
        __syncthreads();

        float* op = out + ((size_t)b * NP + i) * ND;
        for (int d = tid; d < ND; d += 256)
            op[d] = (zsh[i * ND + d] - mu) * rstd * gamma[d] + beta[d];
    }
}

/* ------------------------------------------------------------------ */
extern "C" void kernel_launch(void* const* d_in, const int* in_sizes, int n_in,
                              void* d_out, int out_size)
{
    const float* state = (const float*)d_in[0];
    const float* H1    = (const float*)d_in[1];
    const float* H2    = (const float*)d_in[2];

    MainP mp;
    mp.W[0]   = (const float*)d_in[3];  mp.bias[0] = (const float*)d_in[4];
    mp.W[1]   = (const float*)d_in[5];  mp.bias[1] = (const float*)d_in[6];
    mp.W[2]   = (const float*)d_in[7];  mp.bias[2] = (const float*)d_in[8];

    AuxP ap;
    ap.WC1[0] = (const float*)d_in[9];  ap.bC1[0] = (const float*)d_in[10];
    ap.WC1[1] = (const float*)d_in[11]; ap.bC1[1] = (const float*)d_in[12];
    ap.WC1[2] = (const float*)d_in[13]; ap.bC1[2] = (const float*)d_in[14];
    ap.WC2[0] = (const float*)d_in[15]; ap.bC2[0] = (const float*)d_in[16];
    ap.WC2[1] = (const float*)d_in[17]; ap.bC2[1] = (const float*)d_in[18];
    ap.WC2[2] = (const float*)d_in[19]; ap.bC2[2] = (const float*)d_in[20];

    const float* gamma = (const float*)d_in[21];
    const float* beta  = (const float*)d_in[22];

    dim3 grid((ND + 127) / 128, NM / 128, 3);   /* 22 x 72 x 3 */
    aux_gemm<<<grid, 256>>>(H1, H2, ap);
    main_gemm<<<grid, 256>>>(state, mp);

    const size_t sh = (size_t)NP * ND * sizeof(float);   /* 97200 B */
    cudaFuncSetAttribute(attn_ln, cudaFuncAttributeMaxDynamicSharedMemorySize, (int)sh);
    attn_ln<<<NB, 256, sh>>>(state, gamma, beta, (float*)d_out);
}

// round 5
// speedup vs baseline: 2.2123x; 2.2123x over previous
#include <cuda_runtime.h>
#include <cstdint>

#define NB   1024
#define NP   9
#define ND   2700
#define NDFF 512
#define NM   (NB * NP)
#define TEPS 1e-5f
#define MDSZ ((size_t)NM * (size_t)ND)

/* ---------------- scratch (device statics; no allocs) ---------------- */
__device__ float g_mod[3ULL * NM * ND];
__device__ float g_qkv[3ULL * NM * ND];
__device__ float g_Wt [3ULL * ND * ND];     /* W^T  rounded to tf32 (n-major rows of K) */
__device__ float g_WCt[6ULL * ND * NDFF];   /* WC^T rounded (2700 x 512) x6 */
__device__ float g_Xr [(size_t)NM * ND];    /* X rounded to tf32 */
__device__ float g_H1r[(size_t)NM * NDFF];
__device__ float g_H2r[(size_t)NM * NDFF];

struct MainP { const float* W[3]; const float* bias[3]; };
struct AuxP  { const float* WC1[3]; const float* WC2[3]; const float* bC1[3]; const float* bC2[3]; };

/* ---------------- helpers ---------------- */
__device__ __forceinline__ uint32_t smem_u32(const void* p) {
    uint32_t a;
    asm("{ .reg .u64 t; cvta.to.shared.u64 t, %1; cvt.u32.u64 %0, t; }" : "=r"(a) : "l"(p));
    return a;
}
__device__ __forceinline__ float tf32_round(float x) {
    uint32_t u;
    asm("cvt.rna.tf32.f32 %0, %1;" : "=r"(u) : "f"(x));
    return __uint_as_float(u);
}
__device__ __forceinline__ void cp_async16(uint32_t dst, const void* src, int srcsize) {
    asm volatile("cp.async.cg.shared.global [%0], [%1], 16, %2;"
                 :: "r"(dst), "l"(src), "r"(srcsize) : "memory");
}
#define CP_COMMIT() asm volatile("cp.async.commit_group;" ::: "memory")
#define CP_WAIT1()  asm volatile("cp.async.wait_group 1;" ::: "memory")

#define MMA_TF32(c, av, bv)                                                           \
    asm volatile("mma.sync.aligned.m16n8k8.row.col.f32.tf32.tf32.f32 "                \
        "{%0,%1,%2,%3}, {%4,%5,%6,%7}, {%8,%9}, {%0,%1,%2,%3};"                       \
        : "+f"((c)[0]), "+f"((c)[1]), "+f"((c)[2]), "+f"((c)[3])                      \
        : "r"((av)[0]), "r"((av)[1]), "r"((av)[2]), "r"((av)[3]),                     \
          "r"((bv)[0]), "r"((bv)[1]))

/* smem tile: 128 rows x 36 floats (32 data + 4 pad). 144 B row stride. */
#define ROWF   36
#define TILEF  (128 * ROWF)                 /* floats per operand tile: 4608 */
#define STAGEF (2 * TILEF)                  /* A + B per stage: 9216 floats  */
#define SMEM_BYTES (2 * STAGEF * 4)         /* 2 stages: 73728 B */

/* ---------------- prep kernels ---------------- */
__global__ void round_tf32_k(const float* __restrict__ in, float* __restrict__ out, int n)
{
    const int i0 = (blockIdx.x * 256 + threadIdx.x) * 4;
    if (i0 + 3 < n) {
        float4 v = *(const float4*)(in + i0);
        v.x = tf32_round(v.x); v.y = tf32_round(v.y);
        v.z = tf32_round(v.z); v.w = tf32_round(v.w);
        *(float4*)(out + i0) = v;
    } else {
        for (int i = i0; i < n; i++) out[i] = tf32_round(in[i]);
    }
}

/* transpose + tf32-round: src (R x C) -> dst (C x R) */
__global__ void transpose_round_k(const float* __restrict__ src, float* __restrict__ dst,
                                  int R, int C)
{
    __shared__ float t[32][33];
    const int c0 = blockIdx.x * 32, r0 = blockIdx.y * 32;
    const int x = threadIdx.x, y = threadIdx.y;   /* 32 x 8 */
#pragma unroll
    for (int yy = y; yy < 32; yy += 8) {
        const int r = r0 + yy, c = c0 + x;
        t[yy][x] = (r < R && c < C) ? src[(size_t)r * C + c] : 0.f;
    }
    __syncthreads();
#pragma unroll
    for (int yy = y; yy < 32; yy += 8) {
        const int c = c0 + yy, r = r0 + x;
        if (c < C && r < R) dst[(size_t)c * R + r] = tf32_round(t[x][yy]);
    }
}

/* ---------------- tile loader: 128 threads, thread t owns row t ------- */
__device__ __forceinline__ void load_tile(const float* Arow, int vkbA,
                                          const float* Brow, int vkbB,
                                          uint32_t aoff, uint32_t boff, int tid)
{
    const uint32_t ra = aoff + (uint32_t)tid * 144u;
    const uint32_t rb = boff + (uint32_t)tid * 144u;
#pragma unroll
    for (int q = 0; q < 8; q++) {
        cp_async16(ra + q * 16, Arow + q * 4, (q * 16 < vkbA) ? 16 : 0);
        cp_async16(rb + q * 16, Brow + q * 4, (q * 16 < vkbB) ? 16 : 0);
    }
}

/* ---------------- compute one 32-K chunk for one warp ---------------- */
__device__ __forceinline__ void chunk_mma(const float* As, const float* Bs,
                                          int mw, int nw, int g, int t,
                                          float acc[4][8][4])
{
#pragma unroll
    for (int ks = 0; ks < 4; ks++) {
        const int kb = ks * 8;
        uint32_t a[4][4], b[8][2];
#pragma unroll
        for (int ii = 0; ii < 4; ii++) {
            const float* ap = As + (mw + ii * 16 + g) * ROWF + kb + t;
            a[ii][0] = __float_as_uint(ap[0]);
            a[ii][1] = __float_as_uint(ap[8 * ROWF]);
            a[ii][2] = __float_as_uint(ap[4]);
            a[ii][3] = __float_as_uint(ap[8 * ROWF + 4]);
        }
#pragma unroll
        for (int jj = 0; jj < 8; jj++) {
            const float* bp = Bs + (nw + jj * 8 + g) * ROWF + kb + t;
            b[jj][0] = __float_as_uint(bp[0]);
            b[jj][1] = __float_as_uint(bp[4]);
        }
#pragma unroll
        for (int ii = 0; ii < 4; ii++)
#pragma unroll
            for (int jj = 0; jj < 8; jj++)
                MMA_TF32(acc[ii][jj], a[ii], b[jj]);
    }
}

/* ---------------- main GEMM: qkv = (X @ W + b) * mod ----------------- */
__global__ __launch_bounds__(128, 2)
void main_tc(const float* __restrict__ Xr, MainP p)
{
    extern __shared__ float shm[];
    const uint32_t sbase = smem_u32(shm);
    const int tid = threadIdx.x, lane = tid & 31, wid = tid >> 5;
    const int g = lane >> 2, t = lane & 3;
    const int mw = (wid & 1) * 64, nw = (wid >> 1) * 64;
    const int zi = blockIdx.z, n0 = blockIdx.x * 128, m0 = blockIdx.y * 128;
    const float* Wt = g_Wt + (size_t)zi * ND * ND;
    const int NC = (ND + 31) / 32;           /* 85 */
    const int nrow = n0 + tid;
    const int bok = (nrow < ND);
    const float* Brow0 = bok ? (Wt + (size_t)nrow * ND) : Wt;

    float acc[4][8][4];
#pragma unroll
    for (int i = 0; i < 4; i++)
#pragma unroll
        for (int j = 0; j < 8; j++)
#pragma unroll
            for (int q = 0; q < 4; q++) acc[i][j][q] = 0.f;

    /* prologue: chunks 0,1 */
#pragma unroll
    for (int c = 0; c < 2; c++) {
        const int k0 = c * 32;
        const int vkb = ((ND - k0) >= 32 ? 32 : (ND - k0)) * 4;
        load_tile(Xr + (size_t)(m0 + tid) * ND + k0, vkb,
                  Brow0 + k0, bok ? vkb : 0,
                  sbase + c * (STAGEF * 4), sbase + c * (STAGEF * 4) + TILEF * 4, tid);
        CP_COMMIT();
    }

    for (int i = 0; i < NC; i++) {
        const int s = i & 1;
        CP_WAIT1();
        __syncthreads();
        const float* As = shm + s * STAGEF;
        chunk_mma(As, As + TILEF, mw, nw, g, t, acc);
        __syncthreads();
        const int j = i + 2;
        if (j < NC) {
            const int k0 = j * 32;
            const int vkb = ((ND - k0) >= 32 ? 32 : (ND - k0)) * 4;
            load_tile(Xr + (size_t)(m0 + tid) * ND + k0, vkb,
                      Brow0 + k0, bok ? vkb : 0,
                      sbase + s * (STAGEF * 4), sbase + s * (STAGEF * 4) + TILEF * 4, tid);
        }
        CP_COMMIT();
    }

    /* epilogue */
    const float* bias = p.bias[zi];
#pragma unroll
    for (int ii = 0; ii < 4; ii++) {
#pragma unroll
        for (int half = 0; half < 2; half++) {
            const int m = m0 + mw + ii * 16 + g + half * 8;
            float* dst = g_qkv + (size_t)zi * MDSZ + (size_t)m * ND;
            const float* modp = g_mod + (size_t)zi * MDSZ + (size_t)m * ND;
#pragma unroll
            for (int jj = 0; jj < 8; jj++) {
                const int n = n0 + nw + jj * 8 + t * 2;
                if (n < ND)     dst[n]     = (acc[ii][jj][half * 2]     + bias[n])     * modp[n];
                if (n + 1 < ND) dst[n + 1] = (acc[ii][jj][half * 2 + 1] + bias[n + 1]) * modp[n + 1];
            }
        }
    }
}

/* ---------------- aux GEMM: mod = H1@WC1 + H2@WC2 + bC1 + bC2 -------- */
__global__ __launch_bounds__(128, 2)
void aux_tc(AuxP p)
{
    extern __shared__ float shm[];
    const uint32_t sbase = smem_u32(shm);
    const int tid = threadIdx.x, lane = tid & 31, wid = tid >> 5;
    const int g = lane >> 2, t = lane & 3;
    const int mw = (wid & 1) * 64, nw = (wid >> 1) * 64;
    const int zi = blockIdx.z, n0 = blockIdx.x * 128, m0 = blockIdx.y * 128;
    const float* W1t = g_WCt + (size_t)zi * ND * NDFF;
    const float* W2t = g_WCt + (size_t)(zi + 3) * ND * NDFF;
    const int NC = 32;                       /* 16 chunks per source, K exact */
    const int nrow = n0 + tid;
    const int bok = (nrow < ND);

    float acc[4][8][4];
#pragma unroll
    for (int i = 0; i < 4; i++)
#pragma unroll
        for (int j = 0; j < 8; j++)
#pragma unroll
            for (int q = 0; q < 4; q++) acc[i][j][q] = 0.f;

#pragma unroll
    for (int c = 0; c < 2; c++) {
        const float* A = g_H1r;              /* chunks 0,1 are from H1 */
        const float* W = W1t;
        const int k0 = c * 32;
        load_tile(A + (size_t)(m0 + tid) * NDFF + k0, 128,
                  (bok ? (W + (size_t)nrow * NDFF) : W) + k0, bok ? 128 : 0,
                  sbase + c * (STAGEF * 4), sbase + c * (STAGEF * 4) + TILEF * 4, tid);
        CP_COMMIT();
    }

    for (int i = 0; i < NC; i++) {
        const int s = i & 1;
        CP_WAIT1();
        __syncthreads();
        const float* As = shm + s * STAGEF;
        chunk_mma(As, As + TILEF, mw, nw, g, t, acc);
        __syncthreads();
        const int j = i + 2;
        if (j < NC) {
            const float* A = (j < 16) ? g_H1r : g_H2r;
            const float* W = (j < 16) ? W1t : W2t;
            const int k0 = (j & 15) * 32;
            load_tile(A + (size_t)(m0 + tid) * NDFF + k0, 128,
                      (bok ? (W + (size_t)nrow * NDFF) : W) + k0, bok ? 128 : 0,
                      sbase + s * (STAGEF * 4), sbase + s * (STAGEF * 4) + TILEF * 4, tid);
        }
        CP_COMMIT();
    }

    const float* b1 = p.bC1[zi];
    const float* b2 = p.bC2[zi];
#pragma unroll
    for (int ii = 0; ii < 4; ii++) {
#pragma unroll
        for (int half = 0; half < 2; half++) {
            const int m = m0 + mw + ii * 16 + g + half * 8;
            float* dst = g_mod + (size_t)zi * MDSZ + (size_t)m * ND;
#pragma unroll
            for (int jj = 0; jj < 8; jj++) {
                const int n = n0 + nw + jj * 8 + t * 2;
                if (n < ND)     dst[n]     = acc[ii][jj][half * 2]     + b1[n]     + b2[n];
                if (n + 1 < ND) dst[n + 1] = acc[ii][jj][half * 2 + 1] + b1[n + 1] + b2[n + 1];
            }
        }
    }
}

/* ---------------- attention + residual + LayerNorm ------------------- */
__global__ __launch_bounds__(256)
void attn_ln(const float* __restrict__ X, const float* __restrict__ gamma,
             const float* __restrict__ beta, float* __restrict__ out)
{
    extern __shared__ float zsh[];
    __shared__ float sc[96];
    __shared__ float red[256];

    const int b = blockIdx.x, tid = threadIdx.x;
    const int lane = tid & 31, w = tid >> 5;

    const float* q  = g_qkv +            (size_t)b * NP * ND;
    const float* kx = g_qkv + MDSZ +     (size_t)b * NP * ND;
    const float* v  = g_qkv + 2 * MDSZ + (size_t)b * NP * ND;
    const float* xb = X +                (size_t)b * NP * ND;

    const float scale = rsqrtf((float)ND);
    for (int pr = w; pr < 81; pr += 8) {
        const int i = pr / 9, j = pr % 9;
        const float* qi = q + i * ND;
        const float* kj = kx + j * ND;
        float s = 0.f;
        for (int d = lane; d < ND; d += 32) s = fmaf(qi[d], kj[d], s);
#pragma unroll
        for (int o = 16; o; o >>= 1) s += __shfl_xor_sync(0xffffffffu, s, o);
        if (lane == 0) sc[pr] = s * scale;
    }
    __syncthreads();

    if (tid < 9) {
        float mx = -1e30f;
#pragma unroll
        for (int j = 0; j < 9; j++) mx = fmaxf(mx, sc[tid * 9 + j]);
        float e[9], sum = 0.f;
#pragma unroll
        for (int j = 0; j < 9; j++) { e[j] = expf(sc[tid * 9 + j] - mx); sum += e[j]; }
        const float inv = 1.f / sum;
#pragma unroll
        for (int j = 0; j < 9; j++) sc[tid * 9 + j] = e[j] * inv;
    }
    __syncthreads();

    for (int d = tid; d < ND; d += 256) {
        float vj[9];
#pragma unroll
        for (int j = 0; j < 9; j++) vj[j] = v[j * ND + d];
#pragma unroll
        for (int i = 0; i < 9; i++) {
            float a = xb[i * ND + d];
#pragma unroll
            for (int j = 0; j < 9; j++) a = fmaf(sc[i * 9 + j], vj[j], a);
            zsh[i * ND + d] = a;
        }
    }
    __syncthreads();

    for (int i = 0; i < 9; i++) {
        float s = 0.f;
        for (int d = tid; d < ND; d += 256) s += zsh[i * ND + d];
        red[tid] = s; __syncthreads();
        for (int o = 128; o > 0; o >>= 1) { if (tid < o) red[tid] += red[tid + o]; __syncthreads(); }
        const float mu = red[0] * (1.f / ND);
        __syncthreads();

        float s2 = 0.f;
        for (int d = tid; d < ND; d += 256) { const float tt = zsh[i * ND + d] - mu; s2 = fmaf(tt, tt, s2); }
        red[tid] = s2; __syncthreads();
        for (int o = 128; o > 0; o >>= 1) { if (tid < o) red[tid] += red[tid + o]; __syncthreads(); }
        const float rstd = rsqrtf(red[0] * (1.f / ND) + TEPS);
        __syncthreads();

        float* op = out + ((size_t)b * NP + i) * ND;
        for (int d = tid; d < ND; d += 256)
            op[d] = (zsh[i * ND + d] - mu) * rstd * gamma[d] + beta[d];
    }
}

/* ---------------- launch ---------------- */
extern "C" void kernel_launch(void* const* d_in, const int* in_sizes, int n_in,
                              void* d_out, int out_size)
{
    const float* state = (const float*)d_in[0];
    const float* H1    = (const float*)d_in[1];
    const float* H2    = (const float*)d_in[2];

    MainP mp;
    mp.W[0] = (const float*)d_in[3];  mp.bias[0] = (const float*)d_in[4];
    mp.W[1] = (const float*)d_in[5];  mp.bias[1] = (const float*)d_in[6];
    mp.W[2] = (const float*)d_in[7];  mp.bias[2] = (const float*)d_in[8];

    AuxP ap;
    ap.WC1[0] = (const float*)d_in[9];  ap.bC1[0] = (const float*)d_in[10];
    ap.WC1[1] = (const float*)d_in[11]; ap.bC1[1] = (const float*)d_in[12];
    ap.WC1[2] = (const float*)d_in[13]; ap.bC1[2] = (const float*)d_in[14];
    ap.WC2[0] = (const float*)d_in[15]; ap.bC2[0] = (const float*)d_in[16];
    ap.WC2[1] = (const float*)d_in[17]; ap.bC2[1] = (const float*)d_in[18];
    ap.WC2[2] = (const float*)d_in[19]; ap.bC2[2] = (const float*)d_in[20];

    const float* gamma = (const float*)d_in[21];
    const float* beta  = (const float*)d_in[22];

    float *wt, *wct, *xr, *h1r, *h2r;
    cudaGetSymbolAddress((void**)&wt,  g_Wt);
    cudaGetSymbolAddress((void**)&wct, g_WCt);
    cudaGetSymbolAddress((void**)&xr,  g_Xr);
    cudaGetSymbolAddress((void**)&h1r, g_H1r);
    cudaGetSymbolAddress((void**)&h2r, g_H2r);

    /* prep: round activations, transpose+round weights */
    {
        const int nX = NM * ND, nH = NM * NDFF;
        round_tf32_k<<<(nX + 1023) / 1024, 256>>>(state, xr, nX);
        round_tf32_k<<<(nH + 1023) / 1024, 256>>>(H1, h1r, nH);
        round_tf32_k<<<(nH + 1023) / 1024, 256>>>(H2, h2r, nH);

        dim3 blk(32, 8);
        dim3 g1((ND + 31) / 32, (ND + 31) / 32);
        for (int z = 0; z < 3; z++)
            transpose_round_k<<<g1, blk>>>(mp.W[z], wt + (size_t)z * ND * ND, ND, ND);
        dim3 g2((ND + 31) / 32, (NDFF + 31) / 32);
        for (int z = 0; z < 3; z++)
            transpose_round_k<<<g2, blk>>>(ap.WC1[z], wct + (size_t)z * ND * NDFF, NDFF, ND);
        for (int z = 0; z < 3; z++)
            transpose_round_k<<<g2, blk>>>(ap.WC2[z], wct + (size_t)(z + 3) * ND * NDFF, NDFF, ND);
    }

    cudaFuncSetAttribute(aux_tc,  cudaFuncAttributeMaxDynamicSharedMemorySize, SMEM_BYTES);
    cudaFuncSetAttribute(main_tc, cudaFuncAttributeMaxDynamicSharedMemorySize, SMEM_BYTES);

    dim3 grid((ND + 127) / 128, NM / 128, 3);   /* 22 x 72 x 3 */
    aux_tc<<<grid, 128, SMEM_BYTES>>>(ap);
    main_tc<<<grid, 128, SMEM_BYTES>>>(xr, mp);

    const size_t sh = (size_t)NP * ND * sizeof(float);
    cudaFuncSetAttribute(attn_ln, cudaFuncAttributeMaxDynamicSharedMemorySize, (int)sh);
    attn_ln<<<NB, 256, sh>>>(state, gamma, beta, (float*)d_out);
}